// round 1
// baseline (speedup 1.0000x reference)
#include <cuda_runtime.h>
#include <math.h>

#define BATCH 2
#define CT 64      // thermal channels (= output channels)
#define CO 32      // optical channels (= V dim)
#define ED 64      // embed dim E
#define HI 32
#define WI 32
#define HO 96
#define WO 96
#define NQ (HO*WO)   // 9216

#define MT 32        // keys per smem tile
#define KS_STRIDE 68 // 64 + 4 pad (272B rows, 16B aligned)
#define VS_STRIDE 36 // 32 + 4 pad (144B rows, 16B aligned)

// scratch (allocation-free: __device__ globals)
__device__ float g_q[BATCH*ED*NQ];
__device__ float g_k[BATCH*ED*NQ];
__device__ float g_v[BATCH*CO*NQ];

// ---------------------------------------------------------------------------
// Kernel 1: fused bilinear 3x upsample (half-pixel, edge clamp) + 1x1 Q proj
// ---------------------------------------------------------------------------
__global__ __launch_bounds__(256) void proj_q_kernel(
    const float* __restrict__ xt,   // [B][CT][HI][WI]
    const float* __restrict__ qw,   // [ED][CT]
    const float* __restrict__ qb)   // [ED]
{
    __shared__ float ws[ED*CT];     // 16 KB
    __shared__ float bs[ED];
    int tid = threadIdx.x;
    for (int i = tid; i < ED*CT; i += 256) ws[i] = qw[i];
    if (tid < ED) bs[tid] = qb[tid];
    __syncthreads();

    int idx = blockIdx.x*256 + tid;     // 72 blocks -> 18432 = B*NQ
    int b = idx / NQ, n = idx % NQ;
    int y = n / WO, x = n % WO;

    float sy = (y + 0.5f) * (1.0f/3.0f) - 0.5f;
    float sx = (x + 0.5f) * (1.0f/3.0f) - 0.5f;
    float fy0 = floorf(sy), fx0 = floorf(sx);
    float fy = sy - fy0,    fx = sx - fx0;
    int y0 = (int)fy0, x0 = (int)fx0;
    int y0c = max(y0, 0), y1c = min(y0+1, HI-1);
    int x0c = max(x0, 0), x1c = min(x0+1, WI-1);
    float w00 = (1.f-fy)*(1.f-fx), w01 = (1.f-fy)*fx;
    float w10 = fy*(1.f-fx),       w11 = fy*fx;

    float xv[CT];
    const float* tb = xt + b*CT*HI*WI;
    #pragma unroll
    for (int c = 0; c < CT; c++) {
        const float* p = tb + c*HI*WI;
        xv[c] = w00*p[y0c*WI+x0c] + w01*p[y0c*WI+x1c]
              + w10*p[y1c*WI+x0c] + w11*p[y1c*WI+x1c];
    }

    float* qo = g_q + b*ED*NQ + n;
    for (int e = 0; e < ED; e++) {
        float s = bs[e];
        const float4* w4 = (const float4*)(ws + e*CT);
        #pragma unroll
        for (int c4 = 0; c4 < CT/4; c4++) {
            float4 w = w4[c4];
            s = fmaf(w.x, xv[4*c4+0], s);
            s = fmaf(w.y, xv[4*c4+1], s);
            s = fmaf(w.z, xv[4*c4+2], s);
            s = fmaf(w.w, xv[4*c4+3], s);
        }
        qo[e*NQ] = s;
    }
}

// ---------------------------------------------------------------------------
// Kernel 2: 1x1 K and V projections from optical
// ---------------------------------------------------------------------------
__global__ __launch_bounds__(256) void proj_kv_kernel(
    const float* __restrict__ xo,   // [B][CO][NQ]
    const float* __restrict__ kw,   // [ED][CO]
    const float* __restrict__ kb,
    const float* __restrict__ vw,   // [CO][CO]
    const float* __restrict__ vb)
{
    __shared__ float kws[ED*CO];
    __shared__ float vws[CO*CO];
    __shared__ float kbs[ED], vbs[CO];
    int tid = threadIdx.x;
    for (int i = tid; i < ED*CO; i += 256) kws[i] = kw[i];
    for (int i = tid; i < CO*CO; i += 256) vws[i] = vw[i];
    if (tid < ED) kbs[tid] = kb[tid];
    if (tid < CO) vbs[tid] = vb[tid];
    __syncthreads();

    int idx = blockIdx.x*256 + tid;
    int b = idx / NQ, m = idx % NQ;

    float xv[CO];
    const float* p = xo + b*CO*NQ + m;
    #pragma unroll
    for (int c = 0; c < CO; c++) xv[c] = p[c*NQ];

    float* ko = g_k + b*ED*NQ + m;
    for (int e = 0; e < ED; e++) {
        float s = kbs[e];
        const float4* w4 = (const float4*)(kws + e*CO);
        #pragma unroll
        for (int c4 = 0; c4 < CO/4; c4++) {
            float4 w = w4[c4];
            s = fmaf(w.x, xv[4*c4+0], s);
            s = fmaf(w.y, xv[4*c4+1], s);
            s = fmaf(w.z, xv[4*c4+2], s);
            s = fmaf(w.w, xv[4*c4+3], s);
        }
        ko[e*NQ] = s;
    }
    float* vo = g_v + b*CO*NQ + m;
    for (int o = 0; o < CO; o++) {
        float s = vbs[o];
        const float4* w4 = (const float4*)(vws + o*CO);
        #pragma unroll
        for (int c4 = 0; c4 < CO/4; c4++) {
            float4 w = w4[c4];
            s = fmaf(w.x, xv[4*c4+0], s);
            s = fmaf(w.y, xv[4*c4+1], s);
            s = fmaf(w.z, xv[4*c4+2], s);
            s = fmaf(w.w, xv[4*c4+3], s);
        }
        vo[o*NQ] = s;
    }
}

// ---------------------------------------------------------------------------
// Kernel 3: streaming attention (no-max softmax: scores bounded ~|s|<1)
//           + fused final 1x1 conv + BatchNorm(eval) + ReLU
// one query per thread; q register-resident; K/V streamed via smem tiles
// ---------------------------------------------------------------------------
__global__ __launch_bounds__(128) void attn_kernel(
    const float* __restrict__ ow,    // [CT][CO]
    const float* __restrict__ gam,
    const float* __restrict__ bet,
    const float* __restrict__ mu,
    const float* __restrict__ var,
    float* __restrict__ out)         // [B][CT][NQ]
{
    __shared__ float ks[MT][KS_STRIDE];   // 8704 B
    __shared__ float vs[MT][VS_STRIDE];   // 4608 B
    __shared__ float ows[CT][CO];         // 8192 B
    __shared__ float bn_a[CT], bn_b[CT];

    int tid = threadIdx.x;
    int b = blockIdx.y;
    int n = blockIdx.x*128 + tid;

    for (int i = tid; i < CT*CO; i += 128) ((float*)ows)[i] = ow[i];
    if (tid < CT) {
        float a = gam[tid] * rsqrtf(var[tid] + 1e-5f);
        bn_a[tid] = a;
        bn_b[tid] = bet[tid] - mu[tid]*a;
    }

    // q into registers (coalesced: stride NQ per e, contiguous over tid)
    float q[ED];
    const float* qp = g_q + b*ED*NQ + n;
    #pragma unroll
    for (int e = 0; e < ED; e++) q[e] = qp[e*NQ];

    float num[CO];
    #pragma unroll
    for (int o = 0; o < CO; o++) num[o] = 0.f;
    float den = 0.f;

    const float* kbase = g_k + b*ED*NQ;
    const float* vbase = g_v + b*CO*NQ;

    for (int t = 0; t < NQ/MT; t++) {
        __syncthreads();   // protect previous tile compute (and ows/bn on iter 0)
        int mb = t*MT;
        // K tile: 64e x 32m, transposed -> ks[m][e]
        #pragma unroll
        for (int i = 0; i < (ED*MT)/128; i++) {    // 16 loads/thread
            int id = i*128 + tid;
            int e = id >> 5;
            int m = id & 31;
            ks[m][e] = kbase[e*NQ + mb + m];
        }
        // V tile: 32o x 32m -> vs[m][o]
        #pragma unroll
        for (int i = 0; i < (CO*MT)/128; i++) {    // 8 loads/thread
            int id = i*128 + tid;
            int o = id >> 5;
            int m = id & 31;
            vs[m][o] = vbase[o*NQ + mb + m];
        }
        __syncthreads();

        #pragma unroll 2
        for (int m = 0; m < MT; m++) {
            const float4* k4 = (const float4*)&ks[m][0];
            float sa0 = 0.f, sa1 = 0.f, sa2 = 0.f, sa3 = 0.f;
            #pragma unroll
            for (int e4 = 0; e4 < 16; e4 += 4) {
                float4 a0 = k4[e4+0], a1 = k4[e4+1], a2 = k4[e4+2], a3 = k4[e4+3];
                sa0 = fmaf(a0.x, q[4*e4+0],  fmaf(a0.y, q[4*e4+1],  fmaf(a0.z, q[4*e4+2],  fmaf(a0.w, q[4*e4+3],  sa0))));
                sa1 = fmaf(a1.x, q[4*e4+4],  fmaf(a1.y, q[4*e4+5],  fmaf(a1.z, q[4*e4+6],  fmaf(a1.w, q[4*e4+7],  sa1))));
                sa2 = fmaf(a2.x, q[4*e4+8],  fmaf(a2.y, q[4*e4+9],  fmaf(a2.z, q[4*e4+10], fmaf(a2.w, q[4*e4+11], sa2))));
                sa3 = fmaf(a3.x, q[4*e4+12], fmaf(a3.y, q[4*e4+13], fmaf(a3.z, q[4*e4+14], fmaf(a3.w, q[4*e4+15], sa3))));
            }
            float s = (sa0 + sa1) + (sa2 + sa3);
            float p = __expf(s * 0.125f);      // /sqrt(64); |s/8|<~1 -> no max needed
            den += p;
            const float4* v4 = (const float4*)&vs[m][0];
            #pragma unroll
            for (int o4 = 0; o4 < 8; o4++) {
                float4 v = v4[o4];
                num[4*o4+0] = fmaf(p, v.x, num[4*o4+0]);
                num[4*o4+1] = fmaf(p, v.y, num[4*o4+1]);
                num[4*o4+2] = fmaf(p, v.z, num[4*o4+2]);
                num[4*o4+3] = fmaf(p, v.w, num[4*o4+3]);
            }
        }
    }

    // normalize + final conv + BN + ReLU
    float inv = 1.0f / den;
    #pragma unroll
    for (int o = 0; o < CO; o++) num[o] *= inv;

    float* op = out + b*CT*NQ + n;
    for (int ct = 0; ct < CT; ct++) {
        float g = 0.f;
        const float4* w4 = (const float4*)&ows[ct][0];
        #pragma unroll
        for (int o4 = 0; o4 < 8; o4++) {
            float4 w = w4[o4];
            g = fmaf(w.x, num[4*o4+0], g);
            g = fmaf(w.y, num[4*o4+1], g);
            g = fmaf(w.z, num[4*o4+2], g);
            g = fmaf(w.w, num[4*o4+3], g);
        }
        g = fmaf(g, bn_a[ct], bn_b[ct]);
        op[ct*NQ] = fmaxf(g, 0.f);
    }
}

// ---------------------------------------------------------------------------
extern "C" void kernel_launch(void* const* d_in, const int* in_sizes, int n_in,
                              void* d_out, int out_size)
{
    const float* xt  = (const float*)d_in[0];   // x_thermal
    const float* xo  = (const float*)d_in[1];   // x_optical
    const float* qw  = (const float*)d_in[2];
    const float* qb  = (const float*)d_in[3];
    const float* kw  = (const float*)d_in[4];
    const float* kb  = (const float*)d_in[5];
    const float* vw  = (const float*)d_in[6];
    const float* vb  = (const float*)d_in[7];
    const float* ow  = (const float*)d_in[8];
    const float* gam = (const float*)d_in[9];
    const float* bet = (const float*)d_in[10];
    const float* mu  = (const float*)d_in[11];
    const float* var = (const float*)d_in[12];
    float* out = (float*)d_out;

    proj_q_kernel<<<(BATCH*NQ)/256, 256>>>(xt, qw, qb);
    proj_kv_kernel<<<(BATCH*NQ)/256, 256>>>(xo, kw, kb, vw, vb);
    dim3 g(NQ/128, BATCH);
    attn_kernel<<<g, 128>>>(ow, gam, bet, mu, var, out);
}

// round 2
// speedup vs baseline: 14.2964x; 14.2964x over previous
#include <cuda_runtime.h>
#include <cuda_fp16.h>
#include <cstdint>
#include <math.h>

#define BATCH 2
#define CT 64      // thermal channels (= output channels)
#define CO 32      // optical channels (= V dim)
#define ED 64      // embed dim E
#define HI 32
#define WI 32
#define HO 96
#define WO 96
#define NQ (HO*WO)     // 9216
#define QB 128         // queries per CTA
#define KT 64          // keys per smem tile
#define NTILES (NQ/KT) // 144
#define QSCALE 0.180336880f   // (1/sqrt(64)) * log2(e): softmax becomes exp2(s)

// fp16 scratch (allocation-free: __device__ globals)
__device__ __half g_qh[BATCH*NQ*ED];   // [b][n][e], pre-scaled by QSCALE
__device__ __half g_kh[BATCH*NQ*ED];   // [b][m][e]
__device__ __half g_vh[BATCH*NQ*CO];   // [b][m][o]

// ---------------------------------------------------------------------------
// helpers
// ---------------------------------------------------------------------------
__device__ __forceinline__ uint32_t pack2(float a, float b) {
    __half2 h = __floats2half2_rn(a, b);   // .x = a (low), .y = b (high)
    return *(uint32_t*)&h;
}
__device__ __forceinline__ float ex2(float x) {
    float y; asm("ex2.approx.f32 %0, %1;" : "=f"(y) : "f"(x)); return y;
}
__device__ __forceinline__ void ldsm4(uint32_t* r, uint32_t addr) {
    asm volatile("ldmatrix.sync.aligned.m8n8.x4.shared.b16 {%0,%1,%2,%3}, [%4];"
        : "=r"(r[0]), "=r"(r[1]), "=r"(r[2]), "=r"(r[3]) : "r"(addr));
}
__device__ __forceinline__ void ldsm4t(uint32_t* r, uint32_t addr) {
    asm volatile("ldmatrix.sync.aligned.m8n8.x4.trans.shared.b16 {%0,%1,%2,%3}, [%4];"
        : "=r"(r[0]), "=r"(r[1]), "=r"(r[2]), "=r"(r[3]) : "r"(addr));
}
__device__ __forceinline__ void mma16816(float* c, const uint32_t* a, const uint32_t* b) {
    asm volatile("mma.sync.aligned.m16n8k16.row.col.f32.f16.f16.f32 "
        "{%0,%1,%2,%3}, {%4,%5,%6,%7}, {%8,%9}, {%0,%1,%2,%3};"
        : "+f"(c[0]), "+f"(c[1]), "+f"(c[2]), "+f"(c[3])
        : "r"(a[0]), "r"(a[1]), "r"(a[2]), "r"(a[3]), "r"(b[0]), "r"(b[1]));
}
__device__ __forceinline__ void cpasync16(uint32_t dst, const void* src) {
    asm volatile("cp.async.cg.shared.global [%0], [%1], 16;"
        :: "r"(dst), "l"(__cvta_generic_to_global(src)));
}

// ---------------------------------------------------------------------------
// Kernel 1: bilinear 3x upsample (half-pixel, edge clamp) + 1x1 Q proj -> fp16
// Q is pre-scaled by QSCALE so attention softmax is exp2(score).
// ---------------------------------------------------------------------------
__global__ __launch_bounds__(128) void proj_q_kernel(
    const float* __restrict__ xt, const float* __restrict__ qw,
    const float* __restrict__ qb)
{
    __shared__ float ws[ED*CT];
    __shared__ float bs[ED];
    int tid = threadIdx.x;
    for (int i = tid; i < ED*CT; i += 128) ws[i] = qw[i] * QSCALE;
    if (tid < ED) bs[tid] = qb[tid] * QSCALE;
    __syncthreads();

    int idx = blockIdx.x*128 + tid;     // B*NQ threads
    int b = idx / NQ, n = idx % NQ;
    int y = n / WO, x = n % WO;

    float sy = (y + 0.5f) * (1.0f/3.0f) - 0.5f;
    float sx = (x + 0.5f) * (1.0f/3.0f) - 0.5f;
    float fy0 = floorf(sy), fx0 = floorf(sx);
    float fy = sy - fy0, fx = sx - fx0;
    int y0 = (int)fy0, x0 = (int)fx0;
    int y0c = max(y0, 0), y1c = min(y0+1, HI-1);
    int x0c = max(x0, 0), x1c = min(x0+1, WI-1);
    float w00 = (1.f-fy)*(1.f-fx), w01 = (1.f-fy)*fx;
    float w10 = fy*(1.f-fx),       w11 = fy*fx;

    float xv[CT];
    const float* tb = xt + b*CT*HI*WI;
    #pragma unroll
    for (int c = 0; c < CT; c++) {
        const float* p = tb + c*HI*WI;
        xv[c] = w00*p[y0c*WI+x0c] + w01*p[y0c*WI+x1c]
              + w10*p[y1c*WI+x0c] + w11*p[y1c*WI+x1c];
    }

    uint4* dst = (uint4*)(g_qh + (size_t)idx*ED);
    #pragma unroll
    for (int blk = 0; blk < 8; blk++) {
        float s[8];
        #pragma unroll
        for (int j = 0; j < 8; j++) {
            int e = blk*8 + j;
            float acc = bs[e];
            const float4* w4 = (const float4*)(ws + e*CT);
            #pragma unroll
            for (int c4 = 0; c4 < CT/4; c4++) {
                float4 w = w4[c4];
                acc = fmaf(w.x, xv[4*c4+0], acc);
                acc = fmaf(w.y, xv[4*c4+1], acc);
                acc = fmaf(w.z, xv[4*c4+2], acc);
                acc = fmaf(w.w, xv[4*c4+3], acc);
            }
            s[j] = acc;
        }
        uint4 u;
        u.x = pack2(s[0], s[1]); u.y = pack2(s[2], s[3]);
        u.z = pack2(s[4], s[5]); u.w = pack2(s[6], s[7]);
        dst[blk] = u;
    }
}

// ---------------------------------------------------------------------------
// Kernel 2: 1x1 K and V projections -> fp16, key-major layouts
// ---------------------------------------------------------------------------
__global__ __launch_bounds__(128) void proj_kv_kernel(
    const float* __restrict__ xo,
    const float* __restrict__ kw, const float* __restrict__ kb,
    const float* __restrict__ vw, const float* __restrict__ vb)
{
    __shared__ float kws[ED*CO];
    __shared__ float vws[CO*CO];
    __shared__ float kbs[ED], vbs[CO];
    int tid = threadIdx.x;
    for (int i = tid; i < ED*CO; i += 128) kws[i] = kw[i];
    for (int i = tid; i < CO*CO; i += 128) vws[i] = vw[i];
    if (tid < ED) kbs[tid] = kb[tid];
    if (tid < CO) vbs[tid] = vb[tid];
    __syncthreads();

    int idx = blockIdx.x*128 + tid;
    int b = idx / NQ, m = idx % NQ;

    float xv[CO];
    const float* p = xo + (size_t)b*CO*NQ + m;
    #pragma unroll
    for (int c = 0; c < CO; c++) xv[c] = p[(size_t)c*NQ];

    uint4* kdst = (uint4*)(g_kh + (size_t)idx*ED);
    #pragma unroll
    for (int blk = 0; blk < 8; blk++) {
        float s[8];
        #pragma unroll
        for (int j = 0; j < 8; j++) {
            int e = blk*8 + j;
            float acc = kbs[e];
            const float4* w4 = (const float4*)(kws + e*CO);
            #pragma unroll
            for (int c4 = 0; c4 < CO/4; c4++) {
                float4 w = w4[c4];
                acc = fmaf(w.x, xv[4*c4+0], acc);
                acc = fmaf(w.y, xv[4*c4+1], acc);
                acc = fmaf(w.z, xv[4*c4+2], acc);
                acc = fmaf(w.w, xv[4*c4+3], acc);
            }
            s[j] = acc;
        }
        uint4 u;
        u.x = pack2(s[0], s[1]); u.y = pack2(s[2], s[3]);
        u.z = pack2(s[4], s[5]); u.w = pack2(s[6], s[7]);
        kdst[blk] = u;
    }

    uint4* vdst = (uint4*)(g_vh + (size_t)idx*CO);
    #pragma unroll
    for (int blk = 0; blk < 4; blk++) {
        float s[8];
        #pragma unroll
        for (int j = 0; j < 8; j++) {
            int o = blk*8 + j;
            float acc = vbs[o];
            const float4* w4 = (const float4*)(vws + o*CO);
            #pragma unroll
            for (int c4 = 0; c4 < CO/4; c4++) {
                float4 w = w4[c4];
                acc = fmaf(w.x, xv[4*c4+0], acc);
                acc = fmaf(w.y, xv[4*c4+1], acc);
                acc = fmaf(w.z, xv[4*c4+2], acc);
                acc = fmaf(w.w, xv[4*c4+3], acc);
            }
            s[j] = acc;
        }
        uint4 u;
        u.x = pack2(s[0], s[1]); u.y = pack2(s[2], s[3]);
        u.z = pack2(s[4], s[5]); u.w = pack2(s[6], s[7]);
        vdst[blk] = u;
    }
}

// ---------------------------------------------------------------------------
// Kernel 3: flash-attention via mma.sync (fp16 in / fp32 acc), no-max softmax,
//           fused normalize + 1x1 conv + BN(eval) + ReLU epilogue.
// 256 threads = 8 warps; warp w owns query rows [16w, 16w+16).
// smem layout (static 47104 B, regions reused):
//   [0, 18432)      Q tile fp16 [128][72]       (mainloop prologue)
//   [18432, 36864)  K double buffer [2][64][72] fp16
//   [36864, 47104)  V double buffer [2][64][40] fp16
//   epilogue reuse: [0,16896) O smem f32 [128][33]; [16896,25088) conv W;
//                   [25088,25600) BN a/b
// ---------------------------------------------------------------------------
__global__ __launch_bounds__(256, 1) void attn_kernel(
    const float* __restrict__ ow,
    const float* __restrict__ gam, const float* __restrict__ bet,
    const float* __restrict__ mu,  const float* __restrict__ var,
    float* __restrict__ out)
{
    __shared__ __align__(16) char sm[47104];
    float* osm = (float*)sm;                 // [128][33]
    float* wsm = (float*)(sm + 16896);       // [64][32]
    float* bna = (float*)(sm + 25088);       // [64]
    float* bnb = (float*)(sm + 25344);       // [64]

    const int tid = threadIdx.x;
    const int l = tid & 31, w = tid >> 5;
    const int b = blockIdx.y;
    const int qbase = blockIdx.x * QB;

    uint32_t smb  = (uint32_t)__cvta_generic_to_shared(sm);
    uint32_t qs_b = smb;
    uint32_t ks_b = smb + 18432;
    uint32_t vs_b = smb + 36864;

    // ---- stage Q tile to smem (padded rows of 72 halves = 144B) ----
    {
        const uint4* qsrc = (const uint4*)(g_qh + ((size_t)b*NQ + qbase)*ED);
        #pragma unroll
        for (int i = 0; i < 4; i++) {
            int c = tid + i*256;             // 1024 16B chunks
            int row = c >> 3, c8 = c & 7;
            *(uint4*)(sm + row*144 + c8*16) = qsrc[row*8 + c8];
        }
    }
    __syncthreads();

    // ---- Q fragments: qa[kk][4], kk = e-step (16 e each) ----
    uint32_t qa[4][4];
    {
        int row = 16*w + (l & 15);
        int colh = l >> 4;
        #pragma unroll
        for (int kk = 0; kk < 4; kk++)
            ldsm4(qa[kk], qs_b + row*144 + (16*kk + 8*colh)*2);
    }

    const __half* kg = g_kh + (size_t)b*NQ*ED;
    const __half* vg = g_vh + (size_t)b*NQ*CO;

    auto load_tile = [&](int t, int buf) {
        // K: 64 rows x 128B -> [64][72] halves
        #pragma unroll
        for (int i = 0; i < 2; i++) {
            int c = tid + i*256;
            int row = c >> 3, c8 = c & 7;
            cpasync16(ks_b + buf*9216 + row*144 + c8*16,
                      kg + (size_t)(t*KT + row)*ED + c8*8);
        }
        // V: 64 rows x 64B -> [64][40] halves
        {
            int row = tid >> 2, c4 = tid & 3;
            cpasync16(vs_b + buf*5120 + row*80 + c4*16,
                      vg + (size_t)(t*KT + row)*CO + c4*8);
        }
        asm volatile("cp.async.commit_group;" ::);
    };

    // precomputed per-lane ldmatrix offsets
    const uint32_t k_lane = (uint32_t)((8*(l >> 4) + (l & 7))*144 + ((l & 15) >> 3)*16);
    const int vqd = l >> 3;
    const uint32_t v_lane = (uint32_t)(((vqd & 1)*8 + (l & 7))*80 + (vqd >> 1)*16);

    float oacc[4][4];
    #pragma unroll
    for (int ot = 0; ot < 4; ot++)
        #pragma unroll
        for (int r = 0; r < 4; r++) oacc[ot][r] = 0.f;
    float den0 = 0.f, den1 = 0.f;

    load_tile(0, 0);

    for (int t = 0; t < NTILES; t++) {
        int buf = t & 1;
        if (t + 1 < NTILES) {
            load_tile(t + 1, buf ^ 1);
            asm volatile("cp.async.wait_group 1;" ::);
        } else {
            asm volatile("cp.async.wait_group 0;" ::);
        }
        __syncthreads();

        // ---- S = Q * K^T  (16q x 64keys per warp) ----
        float sc[8][4];
        #pragma unroll
        for (int j = 0; j < 8; j++)
            #pragma unroll
            for (int r = 0; r < 4; r++) sc[j][r] = 0.f;

        uint32_t kbase = ks_b + buf*9216 + k_lane;
        #pragma unroll
        for (int kk = 0; kk < 4; kk++) {
            uint32_t kb[16];
            #pragma unroll
            for (int j2 = 0; j2 < 4; j2++)
                ldsm4(&kb[4*j2], kbase + j2*2304 + kk*32);
            #pragma unroll
            for (int j = 0; j < 8; j++)
                mma16816(sc[j], qa[kk], &kb[2*j]);
        }

        // ---- softmax numerators (no max subtraction: |s| small & bounded) ----
        #pragma unroll
        for (int j = 0; j < 8; j++) {
            float p0 = ex2(sc[j][0]);
            float p1 = ex2(sc[j][1]);
            float p2 = ex2(sc[j][2]);
            float p3 = ex2(sc[j][3]);
            den0 += p0 + p1;
            den1 += p2 + p3;
            sc[j][0] = p0; sc[j][1] = p1; sc[j][2] = p2; sc[j][3] = p3;
        }
        // pack P into A-fragments (C-layout -> A-layout trick)
        uint32_t pa[4][4];
        #pragma unroll
        for (int kk2 = 0; kk2 < 4; kk2++) {
            pa[kk2][0] = pack2(sc[2*kk2][0],   sc[2*kk2][1]);
            pa[kk2][1] = pack2(sc[2*kk2][2],   sc[2*kk2][3]);
            pa[kk2][2] = pack2(sc[2*kk2+1][0], sc[2*kk2+1][1]);
            pa[kk2][3] = pack2(sc[2*kk2+1][2], sc[2*kk2+1][3]);
        }

        // ---- O += P * V ----
        uint32_t vbase = vs_b + buf*5120 + v_lane;
        #pragma unroll
        for (int kk2 = 0; kk2 < 4; kk2++) {
            uint32_t vb[8];
            ldsm4t(&vb[0], vbase + kk2*1280);        // o cols 0..15
            ldsm4t(&vb[4], vbase + kk2*1280 + 32);   // o cols 16..31
            #pragma unroll
            for (int ot = 0; ot < 4; ot++)
                mma16816(oacc[ot], pa[kk2], &vb[2*ot]);
        }
        __syncthreads();   // before buf reuse by next cp.async issue
    }

    // ---- epilogue: normalize, then fused conv+BN+ReLU ----
    den0 += __shfl_xor_sync(0xffffffffu, den0, 1);
    den0 += __shfl_xor_sync(0xffffffffu, den0, 2);
    den1 += __shfl_xor_sync(0xffffffffu, den1, 1);
    den1 += __shfl_xor_sync(0xffffffffu, den1, 2);
    float inv0 = 1.0f / den0, inv1 = 1.0f / den1;

    {
        int g = l >> 2, tig = l & 3;
        int r0 = 16*w + g, r1 = r0 + 8;
        #pragma unroll
        for (int ot = 0; ot < 4; ot++) {
            osm[r0*33 + 8*ot + 2*tig    ] = oacc[ot][0] * inv0;
            osm[r0*33 + 8*ot + 2*tig + 1] = oacc[ot][1] * inv0;
            osm[r1*33 + 8*ot + 2*tig    ] = oacc[ot][2] * inv1;
            osm[r1*33 + 8*ot + 2*tig + 1] = oacc[ot][3] * inv1;
        }
    }
    for (int i = tid; i < CT*CO; i += 256) wsm[i] = ow[i];
    if (tid < CT) {
        float a = gam[tid] * rsqrtf(var[tid] + 1e-5f);
        bna[tid] = a;
        bnb[tid] = bet[tid] - mu[tid]*a;
    }
    __syncthreads();

    {
        int q = tid & 127, h = tid >> 7;
        float a[CO];
        #pragma unroll
        for (int o = 0; o < CO; o++) a[o] = osm[q*33 + o];
        float* op = out + (size_t)b*CT*NQ + qbase + q;
        #pragma unroll 4
        for (int cc = 0; cc < 32; cc++) {
            int ct = h*32 + cc;
            float gsum = 0.f;
            const float4* w4 = (const float4*)(wsm + ct*CO);
            #pragma unroll
            for (int o4 = 0; o4 < CO/4; o4++) {
                float4 wv = w4[o4];
                gsum = fmaf(wv.x, a[4*o4+0], gsum);
                gsum = fmaf(wv.y, a[4*o4+1], gsum);
                gsum = fmaf(wv.z, a[4*o4+2], gsum);
                gsum = fmaf(wv.w, a[4*o4+3], gsum);
            }
            gsum = fmaf(gsum, bna[ct], bnb[ct]);
            op[(size_t)ct*NQ] = fmaxf(gsum, 0.f);
        }
    }
}

// ---------------------------------------------------------------------------
extern "C" void kernel_launch(void* const* d_in, const int* in_sizes, int n_in,
                              void* d_out, int out_size)
{
    const float* xt  = (const float*)d_in[0];
    const float* xo  = (const float*)d_in[1];
    const float* qw  = (const float*)d_in[2];
    const float* qb  = (const float*)d_in[3];
    const float* kw  = (const float*)d_in[4];
    const float* kb  = (const float*)d_in[5];
    const float* vw  = (const float*)d_in[6];
    const float* vb  = (const float*)d_in[7];
    const float* ow  = (const float*)d_in[8];
    const float* gam = (const float*)d_in[9];
    const float* bet = (const float*)d_in[10];
    const float* mu  = (const float*)d_in[11];
    const float* var = (const float*)d_in[12];
    float* out = (float*)d_out;

    proj_q_kernel<<<(BATCH*NQ)/128, 128>>>(xt, qw, qb);
    proj_kv_kernel<<<(BATCH*NQ)/128, 128>>>(xo, kw, kb, vw, vb);
    dim3 g(NQ/QB, BATCH);
    attn_kernel<<<g, 256>>>(ow, gam, bet, mu, var, out);
}

// round 4
// speedup vs baseline: 17.6556x; 1.2350x over previous
#include <cuda_runtime.h>
#include <cuda_fp16.h>
#include <cstdint>
#include <math.h>

#define BATCH 2
#define CT 64      // thermal channels (= output channels)
#define CO 32      // optical channels (= V dim)
#define ED 64      // embed dim E
#define HI 32
#define WI 32
#define HO 96
#define WO 96
#define NQ (HO*WO)     // 9216
#define QB 128         // queries per CTA
#define KT 64          // keys per smem tile
#define NTILES (NQ/KT) // 144
#define QSCALE 0.180336880f   // (1/sqrt(64)) * log2(e): softmax becomes exp2(s)
#define ONES2 0x3C003C00u     // f16x2 {1.0, 1.0}

// fp16 scratch (allocation-free: __device__ globals)
__device__ __half g_qh[BATCH*NQ*ED];   // [b][n][e], pre-scaled by QSCALE
__device__ __half g_kh[BATCH*NQ*ED];   // [b][m][e]
__device__ __half g_vh[BATCH*NQ*CO];   // [b][m][o]

// ---------------------------------------------------------------------------
// helpers
// ---------------------------------------------------------------------------
__device__ __forceinline__ uint32_t pack2(float a, float b) {
    __half2 h = __floats2half2_rn(a, b);
    return *(uint32_t*)&h;
}
__device__ __forceinline__ uint32_t h2ex2(uint32_t x) {   // 2^x per f16 half
    uint32_t y; asm("ex2.approx.f16x2 %0, %1;" : "=r"(y) : "r"(x)); return y;
}
__device__ __forceinline__ void ldsm4(uint32_t* r, uint32_t addr) {
    asm volatile("ldmatrix.sync.aligned.m8n8.x4.shared.b16 {%0,%1,%2,%3}, [%4];"
        : "=r"(r[0]), "=r"(r[1]), "=r"(r[2]), "=r"(r[3]) : "r"(addr));
}
__device__ __forceinline__ void ldsm4t(uint32_t* r, uint32_t addr) {
    asm volatile("ldmatrix.sync.aligned.m8n8.x4.trans.shared.b16 {%0,%1,%2,%3}, [%4];"
        : "=r"(r[0]), "=r"(r[1]), "=r"(r[2]), "=r"(r[3]) : "r"(addr));
}
// f32-accumulator HMMA (for PV and den)
__device__ __forceinline__ void mma16816(float* c, const uint32_t* a, const uint32_t* b) {
    asm volatile("mma.sync.aligned.m16n8k16.row.col.f32.f16.f16.f32 "
        "{%0,%1,%2,%3}, {%4,%5,%6,%7}, {%8,%9}, {%0,%1,%2,%3};"
        : "+f"(c[0]), "+f"(c[1]), "+f"(c[2]), "+f"(c[3])
        : "r"(a[0]), "r"(a[1]), "r"(a[2]), "r"(a[3]), "r"(b[0]), "r"(b[1]));
}
// f16-accumulator HMMA (for S)
__device__ __forceinline__ void mma16816h(uint32_t* c, const uint32_t* a, const uint32_t* b) {
    asm volatile("mma.sync.aligned.m16n8k16.row.col.f16.f16.f16.f16 "
        "{%0,%1}, {%2,%3,%4,%5}, {%6,%7}, {%0,%1};"
        : "+r"(c[0]), "+r"(c[1])
        : "r"(a[0]), "r"(a[1]), "r"(a[2]), "r"(a[3]), "r"(b[0]), "r"(b[1]));
}
__device__ __forceinline__ void cpasync16(uint32_t dst, const void* src) {
    asm volatile("cp.async.cg.shared.global [%0], [%1], 16;"
        :: "r"(dst), "l"(__cvta_generic_to_global(src)));
}

// ---------------------------------------------------------------------------
// Kernel 1 (merged projections): grid.y selects work group
//   y 0..3 : Q  = upsample(x_thermal) @ qw^T + qb   (16 e-outputs per group)
//   y 4..7 : K  = x_optical @ kw^T + kb             (16 e-outputs per group)
//   y 8..9 : V  = x_optical @ vw^T + vb             (16 o-outputs per group)
// ---------------------------------------------------------------------------
__global__ __launch_bounds__(128) void proj_kernel(
    const float* __restrict__ xt, const float* __restrict__ xo,
    const float* __restrict__ qw, const float* __restrict__ qb,
    const float* __restrict__ kw, const float* __restrict__ kb,
    const float* __restrict__ vw, const float* __restrict__ vb)
{
    __shared__ float ws[16*CT];
    __shared__ float bs[16];
    const int tid = threadIdx.x;
    const int grp = blockIdx.y;
    const int idx = blockIdx.x*128 + tid;      // B*NQ threads
    const int b = idx / NQ;

    if (grp < 4) {
        // ---------------- Q: bilinear upsample + project ----------------
        int eb = grp * 16;
        for (int i = tid; i < 16*CT; i += 128) ws[i] = qw[eb*CT + i] * QSCALE;
        if (tid < 16) bs[tid] = qb[eb + tid] * QSCALE;
        __syncthreads();

        int n = idx % NQ;
        int y = n / WO, x = n % WO;
        float sy = (y + 0.5f) * (1.0f/3.0f) - 0.5f;
        float sx = (x + 0.5f) * (1.0f/3.0f) - 0.5f;
        float fy0 = floorf(sy), fx0 = floorf(sx);
        float fy = sy - fy0, fx = sx - fx0;
        int y0 = (int)fy0, x0 = (int)fx0;
        int y0c = max(y0, 0), y1c = min(y0+1, HI-1);
        int x0c = max(x0, 0), x1c = min(x0+1, WI-1);
        float w00 = (1.f-fy)*(1.f-fx), w01 = (1.f-fy)*fx;
        float w10 = fy*(1.f-fx),       w11 = fy*fx;

        float xv[CT];
        const float* tb = xt + b*CT*HI*WI;
        #pragma unroll
        for (int c = 0; c < CT; c++) {
            const float* p = tb + c*HI*WI;
            xv[c] = w00*p[y0c*WI+x0c] + w01*p[y0c*WI+x1c]
                  + w10*p[y1c*WI+x0c] + w11*p[y1c*WI+x1c];
        }
        float s[16];
        #pragma unroll
        for (int j = 0; j < 16; j++) {
            float acc = bs[j];
            const float4* w4 = (const float4*)(ws + j*CT);
            #pragma unroll
            for (int c4 = 0; c4 < CT/4; c4++) {
                float4 w = w4[c4];
                acc = fmaf(w.x, xv[4*c4+0], acc);
                acc = fmaf(w.y, xv[4*c4+1], acc);
                acc = fmaf(w.z, xv[4*c4+2], acc);
                acc = fmaf(w.w, xv[4*c4+3], acc);
            }
            s[j] = acc;
        }
        uint4* dst = (uint4*)(g_qh + (size_t)idx*ED + eb);
        #pragma unroll
        for (int h = 0; h < 2; h++) {
            uint4 u;
            u.x = pack2(s[8*h+0], s[8*h+1]); u.y = pack2(s[8*h+2], s[8*h+3]);
            u.z = pack2(s[8*h+4], s[8*h+5]); u.w = pack2(s[8*h+6], s[8*h+7]);
            dst[h] = u;
        }
    } else {
        // ---------------- K / V projections from x_optical ----------------
        bool isv = grp >= 8;
        int ob = (isv ? (grp-8) : (grp-4)) * 16;
        const float* W  = isv ? vw : kw;
        const float* Bv = isv ? vb : kb;
        for (int i = tid; i < 16*CO; i += 128) ws[i] = W[ob*CO + i];
        if (tid < 16) bs[tid] = Bv[ob + tid];
        __syncthreads();

        int m = idx % NQ;
        float xv[CO];
        const float* p = xo + (size_t)b*CO*NQ + m;
        #pragma unroll
        for (int c = 0; c < CO; c++) xv[c] = p[(size_t)c*NQ];

        float s[16];
        #pragma unroll
        for (int j = 0; j < 16; j++) {
            float acc = bs[j];
            const float4* w4 = (const float4*)(ws + j*CO);
            #pragma unroll
            for (int c4 = 0; c4 < CO/4; c4++) {
                float4 w = w4[c4];
                acc = fmaf(w.x, xv[4*c4+0], acc);
                acc = fmaf(w.y, xv[4*c4+1], acc);
                acc = fmaf(w.z, xv[4*c4+2], acc);
                acc = fmaf(w.w, xv[4*c4+3], acc);
            }
            s[j] = acc;
        }
        __half* dst = (isv ? g_vh + (size_t)idx*CO : g_kh + (size_t)idx*ED) + ob;
        uint4* d4 = (uint4*)dst;
        #pragma unroll
        for (int h = 0; h < 2; h++) {
            uint4 u;
            u.x = pack2(s[8*h+0], s[8*h+1]); u.y = pack2(s[8*h+2], s[8*h+3]);
            u.z = pack2(s[8*h+4], s[8*h+5]); u.w = pack2(s[8*h+6], s[8*h+7]);
            d4[h] = u;
        }
    }
}

// ---------------------------------------------------------------------------
// Kernel 2: flash attention via mma.sync.
//   S in f16 accumulators (C-frag == A-frag layout; no repack),
//   softmax via ex2.approx.f16x2,
//   den via ones-B HMMA into an fp32 accumulator (exact, matches f16 P),
//   fused normalize + 1x1 conv + BN(eval) + ReLU epilogue.
// 256 threads = 8 warps; warp w owns query rows [16w, 16w+16).
// ---------------------------------------------------------------------------
__global__ __launch_bounds__(256, 1) void attn_kernel(
    const float* __restrict__ ow,
    const float* __restrict__ gam, const float* __restrict__ bet,
    const float* __restrict__ mu,  const float* __restrict__ var,
    float* __restrict__ out)
{
    __shared__ __align__(16) char sm[47104];
    float* osm = (float*)sm;                 // [128][33]
    float* wsm = (float*)(sm + 16896);       // [64][32]
    float* bna = (float*)(sm + 25088);       // [64]
    float* bnb = (float*)(sm + 25344);       // [64]

    const int tid = threadIdx.x;
    const int l = tid & 31, w = tid >> 5;
    const int b = blockIdx.y;
    const int qbase = blockIdx.x * QB;

    uint32_t smb  = (uint32_t)__cvta_generic_to_shared(sm);
    uint32_t qs_b = smb;
    uint32_t ks_b = smb + 18432;
    uint32_t vs_b = smb + 36864;

    // ---- stage Q tile to smem (padded rows of 72 halves = 144B) ----
    {
        const uint4* qsrc = (const uint4*)(g_qh + ((size_t)b*NQ + qbase)*ED);
        #pragma unroll
        for (int i = 0; i < 4; i++) {
            int c = tid + i*256;
            int row = c >> 3, c8 = c & 7;
            *(uint4*)(sm + row*144 + c8*16) = qsrc[row*8 + c8];
        }
    }
    __syncthreads();

    // ---- Q fragments ----
    uint32_t qa[4][4];
    {
        int row = 16*w + (l & 15);
        int colh = l >> 4;
        #pragma unroll
        for (int kk = 0; kk < 4; kk++)
            ldsm4(qa[kk], qs_b + row*144 + (16*kk + 8*colh)*2);
    }

    const __half* kg = g_kh + (size_t)b*NQ*ED;
    const __half* vg = g_vh + (size_t)b*NQ*CO;

    auto load_tile = [&](int t, int buf) {
        #pragma unroll
        for (int i = 0; i < 2; i++) {
            int c = tid + i*256;
            int row = c >> 3, c8 = c & 7;
            cpasync16(ks_b + buf*9216 + row*144 + c8*16,
                      kg + (size_t)(t*KT + row)*ED + c8*8);
        }
        {
            int row = tid >> 2, c4 = tid & 3;
            cpasync16(vs_b + buf*5120 + row*80 + c4*16,
                      vg + (size_t)(t*KT + row)*CO + c4*8);
        }
        asm volatile("cp.async.commit_group;" ::);
    };

    const uint32_t k_lane = (uint32_t)((8*(l >> 4) + (l & 7))*144 + ((l & 15) >> 3)*16);
    const int vqd = l >> 3;
    const uint32_t v_lane = (uint32_t)(((vqd & 1)*8 + (l & 7))*80 + (vqd >> 1)*16);

    float oacc[4][4];
    #pragma unroll
    for (int ot = 0; ot < 4; ot++)
        #pragma unroll
        for (int r = 0; r < 4; r++) oacc[ot][r] = 0.f;
    float dacc[4] = {0.f, 0.f, 0.f, 0.f};           // den accumulator (ones-B MMA)
    const uint32_t bones[2] = { ONES2, ONES2 };

    load_tile(0, 0);

    for (int t = 0; t < NTILES; t++) {
        int buf = t & 1;
        if (t + 1 < NTILES) {
            load_tile(t + 1, buf ^ 1);
            asm volatile("cp.async.wait_group 1;" ::);
        } else {
            asm volatile("cp.async.wait_group 0;" ::);
        }
        __syncthreads();

        // ---- S = Q * K^T in f16 accumulators ----
        uint32_t sc[8][2];
        #pragma unroll
        for (int j = 0; j < 8; j++) { sc[j][0] = 0u; sc[j][1] = 0u; }

        uint32_t kbase = ks_b + buf*9216 + k_lane;
        #pragma unroll
        for (int kk = 0; kk < 4; kk++) {
            uint32_t kb[16];
            #pragma unroll
            for (int j2 = 0; j2 < 4; j2++)
                ldsm4(&kb[4*j2], kbase + j2*2304 + kk*32);
            #pragma unroll
            for (int j = 0; j < 8; j++)
                mma16816h(sc[j], qa[kk], &kb[2*j]);
        }

        // ---- P = exp2(S) elementwise on f16x2; C-frag layout == A-frag layout ----
        uint32_t pa[4][4];
        #pragma unroll
        for (int kk2 = 0; kk2 < 4; kk2++) {
            pa[kk2][0] = h2ex2(sc[2*kk2][0]);
            pa[kk2][1] = h2ex2(sc[2*kk2][1]);
            pa[kk2][2] = h2ex2(sc[2*kk2+1][0]);
            pa[kk2][3] = h2ex2(sc[2*kk2+1][1]);
        }

        // ---- O += P * V ;  den += P * 1 ----
        uint32_t vbase = vs_b + buf*5120 + v_lane;
        #pragma unroll
        for (int kk2 = 0; kk2 < 4; kk2++) {
            uint32_t vb[8];
            ldsm4t(&vb[0], vbase + kk2*1280);
            ldsm4t(&vb[4], vbase + kk2*1280 + 32);
            #pragma unroll
            for (int ot = 0; ot < 4; ot++)
                mma16816(oacc[ot], pa[kk2], &vb[2*ot]);
            mma16816(dacc, pa[kk2], bones);
        }
        __syncthreads();
    }

    // ---- epilogue: normalize (den exact from tensor core), conv+BN+ReLU ----
    float inv0 = 1.0f / dacc[0];
    float inv1 = 1.0f / dacc[2];

    {
        int g = l >> 2, tig = l & 3;
        int r0 = 16*w + g, r1 = r0 + 8;
        #pragma unroll
        for (int ot = 0; ot < 4; ot++) {
            osm[r0*33 + 8*ot + 2*tig    ] = oacc[ot][0] * inv0;
            osm[r0*33 + 8*ot + 2*tig + 1] = oacc[ot][1] * inv0;
            osm[r1*33 + 8*ot + 2*tig    ] = oacc[ot][2] * inv1;
            osm[r1*33 + 8*ot + 2*tig + 1] = oacc[ot][3] * inv1;
        }
    }
    for (int i = tid; i < CT*CO; i += 256) wsm[i] = ow[i];
    if (tid < CT) {
        float a = gam[tid] * rsqrtf(var[tid] + 1e-5f);
        bna[tid] = a;
        bnb[tid] = bet[tid] - mu[tid]*a;
    }
    __syncthreads();

    {
        int q = tid & 127, h = tid >> 7;
        float a[CO];
        #pragma unroll
        for (int o = 0; o < CO; o++) a[o] = osm[q*33 + o];
        float* op = out + (size_t)b*CT*NQ + qbase + q;
        #pragma unroll 4
        for (int cc = 0; cc < 32; cc++) {
            int ct = h*32 + cc;
            float gsum = 0.f;
            const float4* w4 = (const float4*)(wsm + ct*CO);
            #pragma unroll
            for (int o4 = 0; o4 < CO/4; o4++) {
                float4 wv = w4[o4];
                gsum = fmaf(wv.x, a[4*o4+0], gsum);
                gsum = fmaf(wv.y, a[4*o4+1], gsum);
                gsum = fmaf(wv.z, a[4*o4+2], gsum);
                gsum = fmaf(wv.w, a[4*o4+3], gsum);
            }
            gsum = fmaf(gsum, bna[ct], bnb[ct]);
            op[(size_t)ct*NQ] = fmaxf(gsum, 0.f);
        }
    }
}

// ---------------------------------------------------------------------------
extern "C" void kernel_launch(void* const* d_in, const int* in_sizes, int n_in,
                              void* d_out, int out_size)
{
    const float* xt  = (const float*)d_in[0];
    const float* xo  = (const float*)d_in[1];
    const float* qw  = (const float*)d_in[2];
    const float* qb  = (const float*)d_in[3];
    const float* kw  = (const float*)d_in[4];
    const float* kb  = (const float*)d_in[5];
    const float* vw  = (const float*)d_in[6];
    const float* vb  = (const float*)d_in[7];
    const float* ow  = (const float*)d_in[8];
    const float* gam = (const float*)d_in[9];
    const float* bet = (const float*)d_in[10];
    const float* mu  = (const float*)d_in[11];
    const float* var = (const float*)d_in[12];
    float* out = (float*)d_out;

    dim3 gp((BATCH*NQ)/128, 10);
    proj_kernel<<<gp, 128>>>(xt, xo, qw, qb, kw, kb, vw, vb);
    dim3 ga(NQ/QB, BATCH);
    attn_kernel<<<ga, 256>>>(ow, gam, bet, mu, var, out);
}

// round 5
// speedup vs baseline: 18.6646x; 1.0572x over previous
#include <cuda_runtime.h>
#include <cuda_fp16.h>
#include <cstdint>
#include <math.h>

#define BATCH 2
#define CT 64      // thermal channels (= output channels)
#define CO 32      // optical channels (= V dim)
#define ED 64      // embed dim E
#define HI 32
#define WI 32
#define HO 96
#define WO 96
#define NQ (HO*WO)     // 9216
#define QB 128         // queries per CTA
#define KT 64          // keys per smem tile
#define NSPLIT 2       // key-dimension split
#define NT2 (NQ/KT/NSPLIT)   // 72 tiles per CTA
#define NQB (NQ/QB)    // 72 query blocks
#define QSCALE 0.180336880f   // (1/sqrt(64)) * log2(e): softmax becomes exp2(s)
#define ONES2 0x3C003C00u     // f16x2 {1.0, 1.0}
#define PSTRIDE 36     // padded row: 32 num + den@32 + pad (144B, 16B aligned)

// scratch (allocation-free: __device__ globals)
__device__ __half g_qh[BATCH*NQ*ED];   // [b][n][e], pre-scaled by QSCALE
__device__ __half g_kh[BATCH*NQ*ED];   // [b][m][e]
__device__ __half g_vh[BATCH*NQ*CO];   // [b][m][o]
__device__ float  g_part[NSPLIT*BATCH*NQB*QB*PSTRIDE];  // split-K partials

// ---------------------------------------------------------------------------
// helpers
// ---------------------------------------------------------------------------
__device__ __forceinline__ uint32_t pack2(float a, float b) {
    __half2 h = __floats2half2_rn(a, b);
    return *(uint32_t*)&h;
}
__device__ __forceinline__ uint32_t h2ex2(uint32_t x) {
    uint32_t y; asm("ex2.approx.f16x2 %0, %1;" : "=r"(y) : "r"(x)); return y;
}
__device__ __forceinline__ void ldsm4(uint32_t* r, uint32_t addr) {
    asm volatile("ldmatrix.sync.aligned.m8n8.x4.shared.b16 {%0,%1,%2,%3}, [%4];"
        : "=r"(r[0]), "=r"(r[1]), "=r"(r[2]), "=r"(r[3]) : "r"(addr));
}
__device__ __forceinline__ void ldsm4t(uint32_t* r, uint32_t addr) {
    asm volatile("ldmatrix.sync.aligned.m8n8.x4.trans.shared.b16 {%0,%1,%2,%3}, [%4];"
        : "=r"(r[0]), "=r"(r[1]), "=r"(r[2]), "=r"(r[3]) : "r"(addr));
}
__device__ __forceinline__ void mma16816(float* c, const uint32_t* a, const uint32_t* b) {
    asm volatile("mma.sync.aligned.m16n8k16.row.col.f32.f16.f16.f32 "
        "{%0,%1,%2,%3}, {%4,%5,%6,%7}, {%8,%9}, {%0,%1,%2,%3};"
        : "+f"(c[0]), "+f"(c[1]), "+f"(c[2]), "+f"(c[3])
        : "r"(a[0]), "r"(a[1]), "r"(a[2]), "r"(a[3]), "r"(b[0]), "r"(b[1]));
}
__device__ __forceinline__ void mma16816h(uint32_t* c, const uint32_t* a, const uint32_t* b) {
    asm volatile("mma.sync.aligned.m16n8k16.row.col.f16.f16.f16.f16 "
        "{%0,%1}, {%2,%3,%4,%5}, {%6,%7}, {%0,%1};"
        : "+r"(c[0]), "+r"(c[1])
        : "r"(a[0]), "r"(a[1]), "r"(a[2]), "r"(a[3]), "r"(b[0]), "r"(b[1]));
}
__device__ __forceinline__ void cpasync16(uint32_t dst, const void* src) {
    asm volatile("cp.async.cg.shared.global [%0], [%1], 16;"
        :: "r"(dst), "l"(__cvta_generic_to_global(src)));
}

// ---------------------------------------------------------------------------
// Kernel 1 (merged projections): grid.y selects work group
//   y 0..3 : Q  (16 e-outputs per group)   y 4..7 : K    y 8..9 : V
// ---------------------------------------------------------------------------
__global__ __launch_bounds__(128) void proj_kernel(
    const float* __restrict__ xt, const float* __restrict__ xo,
    const float* __restrict__ qw, const float* __restrict__ qb,
    const float* __restrict__ kw, const float* __restrict__ kb,
    const float* __restrict__ vw, const float* __restrict__ vb)
{
    __shared__ float ws[16*CT];
    __shared__ float bs[16];
    const int tid = threadIdx.x;
    const int grp = blockIdx.y;
    const int idx = blockIdx.x*128 + tid;
    const int b = idx / NQ;

    if (grp < 4) {
        int eb = grp * 16;
        for (int i = tid; i < 16*CT; i += 128) ws[i] = qw[eb*CT + i] * QSCALE;
        if (tid < 16) bs[tid] = qb[eb + tid] * QSCALE;
        __syncthreads();

        int n = idx % NQ;
        int y = n / WO, x = n % WO;
        float sy = (y + 0.5f) * (1.0f/3.0f) - 0.5f;
        float sx = (x + 0.5f) * (1.0f/3.0f) - 0.5f;
        float fy0 = floorf(sy), fx0 = floorf(sx);
        float fy = sy - fy0, fx = sx - fx0;
        int y0 = (int)fy0, x0 = (int)fx0;
        int y0c = max(y0, 0), y1c = min(y0+1, HI-1);
        int x0c = max(x0, 0), x1c = min(x0+1, WI-1);
        float w00 = (1.f-fy)*(1.f-fx), w01 = (1.f-fy)*fx;
        float w10 = fy*(1.f-fx),       w11 = fy*fx;

        float xv[CT];
        const float* tb = xt + b*CT*HI*WI;
        #pragma unroll
        for (int c = 0; c < CT; c++) {
            const float* p = tb + c*HI*WI;
            xv[c] = w00*p[y0c*WI+x0c] + w01*p[y0c*WI+x1c]
                  + w10*p[y1c*WI+x0c] + w11*p[y1c*WI+x1c];
        }
        float s[16];
        #pragma unroll
        for (int j = 0; j < 16; j++) {
            float acc = bs[j];
            const float4* w4 = (const float4*)(ws + j*CT);
            #pragma unroll
            for (int c4 = 0; c4 < CT/4; c4++) {
                float4 w = w4[c4];
                acc = fmaf(w.x, xv[4*c4+0], acc);
                acc = fmaf(w.y, xv[4*c4+1], acc);
                acc = fmaf(w.z, xv[4*c4+2], acc);
                acc = fmaf(w.w, xv[4*c4+3], acc);
            }
            s[j] = acc;
        }
        uint4* dst = (uint4*)(g_qh + (size_t)idx*ED + eb);
        #pragma unroll
        for (int h = 0; h < 2; h++) {
            uint4 u;
            u.x = pack2(s[8*h+0], s[8*h+1]); u.y = pack2(s[8*h+2], s[8*h+3]);
            u.z = pack2(s[8*h+4], s[8*h+5]); u.w = pack2(s[8*h+6], s[8*h+7]);
            dst[h] = u;
        }
    } else {
        bool isv = grp >= 8;
        int ob = (isv ? (grp-8) : (grp-4)) * 16;
        const float* W  = isv ? vw : kw;
        const float* Bv = isv ? vb : kb;
        for (int i = tid; i < 16*CO; i += 128) ws[i] = W[ob*CO + i];
        if (tid < 16) bs[tid] = Bv[ob + tid];
        __syncthreads();

        int m = idx % NQ;
        float xv[CO];
        const float* p = xo + (size_t)b*CO*NQ + m;
        #pragma unroll
        for (int c = 0; c < CO; c++) xv[c] = p[(size_t)c*NQ];

        float s[16];
        #pragma unroll
        for (int j = 0; j < 16; j++) {
            float acc = bs[j];
            const float4* w4 = (const float4*)(ws + j*CO);
            #pragma unroll
            for (int c4 = 0; c4 < CO/4; c4++) {
                float4 w = w4[c4];
                acc = fmaf(w.x, xv[4*c4+0], acc);
                acc = fmaf(w.y, xv[4*c4+1], acc);
                acc = fmaf(w.z, xv[4*c4+2], acc);
                acc = fmaf(w.w, xv[4*c4+3], acc);
            }
            s[j] = acc;
        }
        __half* dst = (isv ? g_vh + (size_t)idx*CO : g_kh + (size_t)idx*ED) + ob;
        uint4* d4 = (uint4*)dst;
        #pragma unroll
        for (int h = 0; h < 2; h++) {
            uint4 u;
            u.x = pack2(s[8*h+0], s[8*h+1]); u.y = pack2(s[8*h+2], s[8*h+3]);
            u.z = pack2(s[8*h+4], s[8*h+5]); u.w = pack2(s[8*h+6], s[8*h+7]);
            d4[h] = u;
        }
    }
}

// ---------------------------------------------------------------------------
// Kernel 2: split-K flash attention (mma.sync). Each CTA covers half the keys
// and emits unnormalized (num[32], den) partials (no-max softmax is additive).
// grid = (72 qblocks, BATCH, NSPLIT); 2 CTAs/SM -> 4 warps/SMSP.
// ---------------------------------------------------------------------------
__global__ __launch_bounds__(256, 2) void attn_kernel()
{
    __shared__ __align__(16) char sm[47104];
    float* osm = (float*)sm;                 // epilogue overlay [128][36] = 18432B

    const int tid = threadIdx.x;
    const int l = tid & 31, w = tid >> 5;
    const int b = blockIdx.y;
    const int z = blockIdx.z;
    const int qbase = blockIdx.x * QB;

    uint32_t smb  = (uint32_t)__cvta_generic_to_shared(sm);
    uint32_t qs_b = smb;
    uint32_t ks_b = smb + 18432;
    uint32_t vs_b = smb + 36864;

    // ---- stage Q tile to smem (rows of 72 halves = 144B) ----
    {
        const uint4* qsrc = (const uint4*)(g_qh + ((size_t)b*NQ + qbase)*ED);
        #pragma unroll
        for (int i = 0; i < 4; i++) {
            int c = tid + i*256;
            int row = c >> 3, c8 = c & 7;
            *(uint4*)(sm + row*144 + c8*16) = qsrc[row*8 + c8];
        }
    }
    __syncthreads();

    uint32_t qa[4][4];
    {
        int row = 16*w + (l & 15);
        int colh = l >> 4;
        #pragma unroll
        for (int kk = 0; kk < 4; kk++)
            ldsm4(qa[kk], qs_b + row*144 + (16*kk + 8*colh)*2);
    }

    const __half* kg = g_kh + (size_t)b*NQ*ED + (size_t)z*NT2*KT*ED;
    const __half* vg = g_vh + (size_t)b*NQ*CO + (size_t)z*NT2*KT*CO;

    auto load_tile = [&](int t, int buf) {
        #pragma unroll
        for (int i = 0; i < 2; i++) {
            int c = tid + i*256;
            int row = c >> 3, c8 = c & 7;
            cpasync16(ks_b + buf*9216 + row*144 + c8*16,
                      kg + (size_t)(t*KT + row)*ED + c8*8);
        }
        {
            int row = tid >> 2, c4 = tid & 3;
            cpasync16(vs_b + buf*5120 + row*80 + c4*16,
                      vg + (size_t)(t*KT + row)*CO + c4*8);
        }
        asm volatile("cp.async.commit_group;" ::);
    };

    const uint32_t k_lane = (uint32_t)((8*(l >> 4) + (l & 7))*144 + ((l & 15) >> 3)*16);
    const int vqd = l >> 3;
    const uint32_t v_lane = (uint32_t)(((vqd & 1)*8 + (l & 7))*80 + (vqd >> 1)*16);

    float oacc[4][4];
    #pragma unroll
    for (int ot = 0; ot < 4; ot++)
        #pragma unroll
        for (int r = 0; r < 4; r++) oacc[ot][r] = 0.f;
    float dacc[4] = {0.f, 0.f, 0.f, 0.f};
    const uint32_t bones[2] = { ONES2, ONES2 };

    load_tile(0, 0);

    for (int t = 0; t < NT2; t++) {
        int buf = t & 1;
        if (t + 1 < NT2) {
            load_tile(t + 1, buf ^ 1);
            asm volatile("cp.async.wait_group 1;" ::);
        } else {
            asm volatile("cp.async.wait_group 0;" ::);
        }
        __syncthreads();

        // S = Q K^T in f16 accumulators
        uint32_t sc[8][2];
        #pragma unroll
        for (int j = 0; j < 8; j++) { sc[j][0] = 0u; sc[j][1] = 0u; }

        uint32_t kbase = ks_b + buf*9216 + k_lane;
        #pragma unroll
        for (int kk = 0; kk < 4; kk++) {
            uint32_t kb[16];
            #pragma unroll
            for (int j2 = 0; j2 < 4; j2++)
                ldsm4(&kb[4*j2], kbase + j2*2304 + kk*32);
            #pragma unroll
            for (int j = 0; j < 8; j++)
                mma16816h(sc[j], qa[kk], &kb[2*j]);
        }

        // P = exp2(S); f16 C-frag layout == A-frag layout
        uint32_t pa[4][4];
        #pragma unroll
        for (int kk2 = 0; kk2 < 4; kk2++) {
            pa[kk2][0] = h2ex2(sc[2*kk2][0]);
            pa[kk2][1] = h2ex2(sc[2*kk2][1]);
            pa[kk2][2] = h2ex2(sc[2*kk2+1][0]);
            pa[kk2][3] = h2ex2(sc[2*kk2+1][1]);
        }

        // O += P V ; den += P 1
        uint32_t vbase = vs_b + buf*5120 + v_lane;
        #pragma unroll
        for (int kk2 = 0; kk2 < 4; kk2++) {
            uint32_t vb[8];
            ldsm4t(&vb[0], vbase + kk2*1280);
            ldsm4t(&vb[4], vbase + kk2*1280 + 32);
            #pragma unroll
            for (int ot = 0; ot < 4; ot++)
                mma16816(oacc[ot], pa[kk2], &vb[2*ot]);
            mma16816(dacc, pa[kk2], bones);
        }
        __syncthreads();
    }

    // ---- write unnormalized partials (num[32] + den) via smem staging ----
    {
        int g = l >> 2, tig = l & 3;
        int r0 = 16*w + g, r1 = r0 + 8;
        #pragma unroll
        for (int ot = 0; ot < 4; ot++) {
            osm[r0*PSTRIDE + 8*ot + 2*tig    ] = oacc[ot][0];
            osm[r0*PSTRIDE + 8*ot + 2*tig + 1] = oacc[ot][1];
            osm[r1*PSTRIDE + 8*ot + 2*tig    ] = oacc[ot][2];
            osm[r1*PSTRIDE + 8*ot + 2*tig + 1] = oacc[ot][3];
        }
        if (tig == 0) {
            osm[r0*PSTRIDE + 32] = dacc[0];
            osm[r1*PSTRIDE + 32] = dacc[2];
        }
    }
    __syncthreads();
    {
        // ctaLinear = (z*BATCH + b)*NQB + qblock
        float* dst = g_part + (size_t)((z*BATCH + b)*NQB + blockIdx.x) * (QB*PSTRIDE);
        #pragma unroll
        for (int i = 0; i < (QB*PSTRIDE)/256; i++)
            dst[tid + i*256] = osm[tid + i*256];
    }
}

// ---------------------------------------------------------------------------
// Kernel 3: combine split-K partials, normalize, fused conv + BN + ReLU
// grid = 144 (= BATCH*NQB), 128 threads, one query per thread
// ---------------------------------------------------------------------------
__global__ __launch_bounds__(128) void reduce_kernel(
    const float* __restrict__ ow,
    const float* __restrict__ gam, const float* __restrict__ bet,
    const float* __restrict__ mu,  const float* __restrict__ var,
    float* __restrict__ out)
{
    __shared__ float wsm[CT*CO];
    __shared__ float bna[CT], bnb[CT];
    const int tid = threadIdx.x;
    const int r = blockIdx.x;            // b*NQB + qblock
    const int b = r / NQB;
    const int qbase = (r % NQB) * QB;

    for (int i = tid; i < CT*CO; i += 128) wsm[i] = ow[i];
    if (tid < CT) {
        float a = gam[tid] * rsqrtf(var[tid] + 1e-5f);
        bna[tid] = a;
        bnb[tid] = bet[tid] - mu[tid]*a;
    }
    __syncthreads();

    const float* p0 = g_part + (size_t)r * (QB*PSTRIDE) + tid*PSTRIDE;
    const float* p1 = p0 + (size_t)BATCH*NQB*QB*PSTRIDE;

    float den = p0[32] + p1[32];
    float inv = 1.0f / den;
    float a[CO];
    const float4* q0 = (const float4*)p0;
    const float4* q1 = (const float4*)p1;
    #pragma unroll
    for (int o4 = 0; o4 < CO/4; o4++) {
        float4 u = q0[o4], v = q1[o4];
        a[4*o4+0] = (u.x + v.x) * inv;
        a[4*o4+1] = (u.y + v.y) * inv;
        a[4*o4+2] = (u.z + v.z) * inv;
        a[4*o4+3] = (u.w + v.w) * inv;
    }

    float* op = out + (size_t)b*CT*NQ + qbase + tid;
    #pragma unroll 4
    for (int ct = 0; ct < CT; ct++) {
        float g = 0.f;
        const float4* w4 = (const float4*)(wsm + ct*CO);
        #pragma unroll
        for (int o4 = 0; o4 < CO/4; o4++) {
            float4 wv = w4[o4];
            g = fmaf(wv.x, a[4*o4+0], g);
            g = fmaf(wv.y, a[4*o4+1], g);
            g = fmaf(wv.z, a[4*o4+2], g);
            g = fmaf(wv.w, a[4*o4+3], g);
        }
        g = fmaf(g, bna[ct], bnb[ct]);
        op[(size_t)ct*NQ] = fmaxf(g, 0.f);
    }
}

// ---------------------------------------------------------------------------
extern "C" void kernel_launch(void* const* d_in, const int* in_sizes, int n_in,
                              void* d_out, int out_size)
{
    const float* xt  = (const float*)d_in[0];
    const float* xo  = (const float*)d_in[1];
    const float* qw  = (const float*)d_in[2];
    const float* qb  = (const float*)d_in[3];
    const float* kw  = (const float*)d_in[4];
    const float* kb  = (const float*)d_in[5];
    const float* vw  = (const float*)d_in[6];
    const float* vb  = (const float*)d_in[7];
    const float* ow  = (const float*)d_in[8];
    const float* gam = (const float*)d_in[9];
    const float* bet = (const float*)d_in[10];
    const float* mu  = (const float*)d_in[11];
    const float* var = (const float*)d_in[12];
    float* out = (float*)d_out;

    dim3 gp((BATCH*NQ)/128, 10);
    proj_kernel<<<gp, 128>>>(xt, xo, qw, qb, kw, kb, vw, vb);
    dim3 ga(NQB, BATCH, NSPLIT);
    attn_kernel<<<ga, 256>>>();
    reduce_kernel<<<BATCH*NQB, 128>>>(ow, gam, bet, mu, var, out);
}